// round 9
// baseline (speedup 1.0000x reference)
#include <cuda_runtime.h>
#include <cuda_bf16.h>

#define MAXN 50000
#define MAXE 800000
#define CH   64
#define NG   64

// ---------------- scratch (device globals) ---------------------------------
__device__ __align__(16) float g_dinv[MAXN];
__device__ __align__(16) float g_selfnorm[MAXN];
__device__ __align__(16) int   g_cnt_i[MAXN];
__device__ __align__(16) int   g_rowptr[MAXN + 1];
__device__ __align__(16) int   g_cursor[MAXN];
__device__ __align__(16) int   g_blocksum[64];
__device__ __align__(16) int   g_blockoff[64];
__device__ __align__(16) int2  g_cedge[MAXE];      // {src, w-as-int-bits}
__device__ __align__(16) float g_hraw[MAXN * CH];
__device__ __align__(16) float g_skip[MAXN * CH];
__device__ __align__(16) float g_h   [MAXN * CH];
__device__ __align__(16) float g_pooled[NG * CH];
__device__ __align__(16) float g_cntf[NG];

// ---------------- f32x2 helpers --------------------------------------------
typedef unsigned long long u64;

__device__ __forceinline__ u64 ffma2(u64 a, u64 b, u64 c) {
    u64 d;
    asm("fma.rn.f32x2 %0, %1, %2, %3;" : "=l"(d) : "l"(a), "l"(b), "l"(c));
    return d;
}
__device__ __forceinline__ u64 splat2(float x) {
    u64 d;
    asm("mov.b64 %0, {%1, %1};" : "=l"(d) : "f"(x));
    return d;
}

// ---------------- build CSR ------------------------------------------------

__global__ void k_zero(int n) {
    int i = blockIdx.x * blockDim.x + threadIdx.x;
    if (i < n)       g_cnt_i[i] = 0;
    if (i < NG * CH) g_pooled[i] = 0.0f;
    if (i < NG)      g_cntf[i] = 0.0f;
}

// degree histogram + per-graph node counts fused
__global__ void k_hist(const int* __restrict__ dst, int nE,
                       const int* __restrict__ batch, int n) {
    int e = blockIdx.x * blockDim.x + threadIdx.x;
    if (e < nE) atomicAdd(&g_cnt_i[dst[e]], 1);
    if (e < n)  atomicAdd(&g_cntf[batch[e]], 1.0f);
}

// scan pass 1 (block reduce) + dinv/selfnorm fused
__global__ void k_scan_p1(int n) {
    __shared__ int sh[1024];
    int i = blockIdx.x * 1024 + threadIdx.x;
    int c = (i < n) ? g_cnt_i[i] : 0;
    if (i < n) {
        float r = rsqrtf((float)c + 1.0f);   // deg incl. self-loop
        g_dinv[i] = r;
        g_selfnorm[i] = r * r;
    }
    sh[threadIdx.x] = c;
    __syncthreads();
    #pragma unroll
    for (int s = 512; s > 0; s >>= 1) {
        if (threadIdx.x < s) sh[threadIdx.x] += sh[threadIdx.x + s];
        __syncthreads();
    }
    if (threadIdx.x == 0) g_blocksum[blockIdx.x] = sh[0];
}

__global__ void k_scan_p2(int nB) {
    __shared__ int sh[64];
    int t = threadIdx.x;
    int v = (t < nB) ? g_blocksum[t] : 0;
    sh[t] = v;
    __syncthreads();
    #pragma unroll
    for (int off = 1; off < 64; off <<= 1) {
        int u = (t >= off) ? sh[t - off] : 0;
        __syncthreads();
        sh[t] += u;
        __syncthreads();
    }
    if (t < nB) g_blockoff[t] = sh[t] - v;   // exclusive
}

__global__ void k_scan_p3(int n) {
    __shared__ int sh[1024];
    int i = blockIdx.x * 1024 + threadIdx.x;
    int v = (i < n) ? g_cnt_i[i] : 0;
    sh[threadIdx.x] = v;
    __syncthreads();
    #pragma unroll
    for (int off = 1; off < 1024; off <<= 1) {
        int u = (threadIdx.x >= off) ? sh[threadIdx.x - off] : 0;
        __syncthreads();
        sh[threadIdx.x] += u;
        __syncthreads();
    }
    int ex = g_blockoff[blockIdx.x] + sh[threadIdx.x] - v;
    if (i < n) { g_rowptr[i] = ex; g_cursor[i] = ex; }
    if (i == n - 1) g_rowptr[n] = ex + v;
}

__global__ void k_place(const int* __restrict__ src, const int* __restrict__ dst, int nE) {
    int e = blockIdx.x * blockDim.x + threadIdx.x;
    if (e >= nE) return;
    int s = src[e], d = dst[e];
    int pos = atomicAdd(&g_cursor[d], 1);
    float w = g_dinv[s] * g_dinv[d];
    g_cedge[pos] = make_int2(s, __float_as_int(w));
}

// ---------------- GEMM (f32x2): X[n,64] @ W[64,64], 128-row tiles ----------
// 256 threads: tx=tid&7 (8 cols), ty=tid>>3 (4 rows) -> 4x8 outputs/thread.
__global__ void k_gemm(const float* __restrict__ X, const float* __restrict__ W,
                       int n, float* __restrict__ OUT)
{
    __shared__ __align__(16) float Ws[64 * 64];
    __shared__ __align__(16) float Xs[128 * 65];

    int tid = threadIdx.x;
    int row0 = blockIdx.x * 128;

    {
        const float4* W4 = (const float4*)W;
        float4* Ws4 = (float4*)Ws;
        for (int i = tid; i < 1024; i += 256) Ws4[i] = W4[i];
    }
    for (int i = tid; i < 2048; i += 256) {
        int r  = i >> 4;           // 0..127
        int c4 = (i & 15) << 2;
        int gr = row0 + r;
        float4 v = make_float4(0.f, 0.f, 0.f, 0.f);
        if (gr < n) v = *(const float4*)(X + gr * 64 + c4);
        float* p = &Xs[r * 65 + c4];
        p[0] = v.x; p[1] = v.y; p[2] = v.z; p[3] = v.w;
    }
    __syncthreads();

    int tx = tid & 7;     // 8 col groups of 8
    int ty = tid >> 3;    // 32 row groups of 4

    u64 A[4][4] = {};     // [row][colpair], each u64 = 2 packed fp32

    #pragma unroll
    for (int k = 0; k < 64; k++) {
        ulonglong2 w01 = *(const ulonglong2*)&Ws[k * 64 + tx * 8];
        ulonglong2 w23 = *(const ulonglong2*)&Ws[k * 64 + tx * 8 + 4];
        #pragma unroll
        for (int i = 0; i < 4; i++) {
            u64 x2 = splat2(Xs[(ty * 4 + i) * 65 + k]);
            A[i][0] = ffma2(x2, w01.x, A[i][0]);
            A[i][1] = ffma2(x2, w01.y, A[i][1]);
            A[i][2] = ffma2(x2, w23.x, A[i][2]);
            A[i][3] = ffma2(x2, w23.y, A[i][3]);
        }
    }

    int c0 = tx * 8;
    #pragma unroll
    for (int i = 0; i < 4; i++) {
        int r = row0 + ty * 4 + i;
        if (r >= n) break;
        *(ulonglong2*)(OUT + r * 64 + c0)     = make_ulonglong2(A[i][0], A[i][1]);
        *(ulonglong2*)(OUT + r * 64 + c0 + 4) = make_ulonglong2(A[i][2], A[i][3]);
    }
}

// ---------------- dual GEMM (f32x2): OUTa = X@Wa, OUTb = relu(X@Wb+bb) -----
__global__ void k_gemm2(const float* __restrict__ X,
                        const float* __restrict__ Wa,
                        const float* __restrict__ Wb, const float* __restrict__ bb,
                        int n, float* __restrict__ OUTa, float* __restrict__ OUTb)
{
    __shared__ __align__(16) float Wsa[64 * 64];
    __shared__ __align__(16) float Wsb[64 * 64];
    __shared__ __align__(16) float Xs[128 * 65];

    int tid = threadIdx.x;
    int row0 = blockIdx.x * 128;

    {
        const float4* Wa4 = (const float4*)Wa;
        const float4* Wb4 = (const float4*)Wb;
        float4* a4 = (float4*)Wsa;
        float4* b4 = (float4*)Wsb;
        for (int i = tid; i < 1024; i += 256) { a4[i] = Wa4[i]; b4[i] = Wb4[i]; }
    }
    for (int i = tid; i < 2048; i += 256) {
        int r  = i >> 4;
        int c4 = (i & 15) << 2;
        int gr = row0 + r;
        float4 v = make_float4(0.f, 0.f, 0.f, 0.f);
        if (gr < n) v = *(const float4*)(X + gr * 64 + c4);
        float* p = &Xs[r * 65 + c4];
        p[0] = v.x; p[1] = v.y; p[2] = v.z; p[3] = v.w;
    }
    __syncthreads();

    int tx = tid & 7;
    int ty = tid >> 3;

    u64 A[4][4] = {}, B[4][4] = {};

    #pragma unroll
    for (int k = 0; k < 64; k++) {
        ulonglong2 wa01 = *(const ulonglong2*)&Wsa[k * 64 + tx * 8];
        ulonglong2 wa23 = *(const ulonglong2*)&Wsa[k * 64 + tx * 8 + 4];
        ulonglong2 wb01 = *(const ulonglong2*)&Wsb[k * 64 + tx * 8];
        ulonglong2 wb23 = *(const ulonglong2*)&Wsb[k * 64 + tx * 8 + 4];
        #pragma unroll
        for (int i = 0; i < 4; i++) {
            u64 x2 = splat2(Xs[(ty * 4 + i) * 65 + k]);
            A[i][0] = ffma2(x2, wa01.x, A[i][0]);
            A[i][1] = ffma2(x2, wa01.y, A[i][1]);
            A[i][2] = ffma2(x2, wa23.x, A[i][2]);
            A[i][3] = ffma2(x2, wa23.y, A[i][3]);
            B[i][0] = ffma2(x2, wb01.x, B[i][0]);
            B[i][1] = ffma2(x2, wb01.y, B[i][1]);
            B[i][2] = ffma2(x2, wb23.x, B[i][2]);
            B[i][3] = ffma2(x2, wb23.y, B[i][3]);
        }
    }

    int c0 = tx * 8;
    float4 bv0 = *(const float4*)(bb + c0);
    float4 bv1 = *(const float4*)(bb + c0 + 4);
    #pragma unroll
    for (int i = 0; i < 4; i++) {
        int r = row0 + ty * 4 + i;
        if (r >= n) break;
        *(ulonglong2*)(OUTa + r * 64 + c0)     = make_ulonglong2(A[i][0], A[i][1]);
        *(ulonglong2*)(OUTa + r * 64 + c0 + 4) = make_ulonglong2(A[i][2], A[i][3]);

        float2 p0 = *(float2*)&B[i][0];
        float2 p1 = *(float2*)&B[i][1];
        float2 p2 = *(float2*)&B[i][2];
        float2 p3 = *(float2*)&B[i][3];
        float4 o0 = make_float4(fmaxf(p0.x + bv0.x, 0.f), fmaxf(p0.y + bv0.y, 0.f),
                                fmaxf(p1.x + bv0.z, 0.f), fmaxf(p1.y + bv0.w, 0.f));
        float4 o1 = make_float4(fmaxf(p2.x + bv1.x, 0.f), fmaxf(p2.y + bv1.y, 0.f),
                                fmaxf(p3.x + bv1.z, 0.f), fmaxf(p3.y + bv1.w, 0.f));
        *(float4*)(OUTb + r * 64 + c0)     = o0;
        *(float4*)(OUTb + r * 64 + c0 + 4) = o1;
    }
}

// ---------------- fused GCN aggregate --------------------------------------
// OUT[d] = relu( sum_{e in CSR(d)} w_e*H[src_e] + selfnorm[d]*H[d] + b ) + SKIP[d]
// if DO_POOL: red-add OUT row into g_pooled[batch[d]]. 16 threads/node.
template<int DO_POOL>
__global__ void k_agg(const float* __restrict__ H, const float* __restrict__ SKIP,
                      float* __restrict__ OUT, const float* __restrict__ b,
                      const int* __restrict__ batch, int n)
{
    int t = blockIdx.x * blockDim.x + threadIdx.x;
    int node = t >> 4;
    if (node >= n) return;
    int c4 = (t & 15) << 2;

    int beg = g_rowptr[node];
    int end = g_rowptr[node + 1];

    float sn = g_selfnorm[node];
    float4 hd = *(const float4*)(H + node * 64 + c4);
    float4 acc0 = make_float4(sn * hd.x, sn * hd.y, sn * hd.z, sn * hd.w);
    float4 acc1 = make_float4(0.f, 0.f, 0.f, 0.f);

    int j = beg;
    for (; j + 1 < end; j += 2) {
        int2 e0 = __ldg(&g_cedge[j]);
        int2 e1 = __ldg(&g_cedge[j + 1]);
        float w0 = __int_as_float(e0.y);
        float w1 = __int_as_float(e1.y);
        float4 h0 = *(const float4*)(H + e0.x * 64 + c4);
        float4 h1 = *(const float4*)(H + e1.x * 64 + c4);
        acc0.x = fmaf(w0, h0.x, acc0.x); acc1.x = fmaf(w1, h1.x, acc1.x);
        acc0.y = fmaf(w0, h0.y, acc0.y); acc1.y = fmaf(w1, h1.y, acc1.y);
        acc0.z = fmaf(w0, h0.z, acc0.z); acc1.z = fmaf(w1, h1.z, acc1.z);
        acc0.w = fmaf(w0, h0.w, acc0.w); acc1.w = fmaf(w1, h1.w, acc1.w);
    }
    if (j < end) {
        int2 e = __ldg(&g_cedge[j]);
        float w = __int_as_float(e.y);
        float4 hv = *(const float4*)(H + e.x * 64 + c4);
        acc0.x = fmaf(w, hv.x, acc0.x);
        acc0.y = fmaf(w, hv.y, acc0.y);
        acc0.z = fmaf(w, hv.z, acc0.z);
        acc0.w = fmaf(w, hv.w, acc0.w);
    }
    acc0.x += acc1.x; acc0.y += acc1.y; acc0.z += acc1.z; acc0.w += acc1.w;

    float4 bv = *(const float4*)(b + c4);
    float4 sk = *(const float4*)(SKIP + node * 64 + c4);
    float4 o = make_float4(fmaxf(acc0.x + bv.x, 0.f) + sk.x,
                           fmaxf(acc0.y + bv.y, 0.f) + sk.y,
                           fmaxf(acc0.z + bv.z, 0.f) + sk.z,
                           fmaxf(acc0.w + bv.w, 0.f) + sk.w);
    *(float4*)(OUT + node * 64 + c4) = o;

    if (DO_POOL) {
        int g = batch[node];
        float* p = g_pooled + g * 64 + c4;
        asm volatile("red.global.add.v4.f32 [%0], {%1,%2,%3,%4};"
                     :: "l"(p), "f"(o.x), "f"(o.y), "f"(o.z), "f"(o.w)
                     : "memory");
    }
}

__global__ void k_final(const float* __restrict__ Wf, const float* __restrict__ bf,
                        float* __restrict__ out)
{
    int g = threadIdx.x;
    if (g >= NG) return;
    float cnt = fmaxf(g_cntf[g], 1.0f);
    float acc = 0.f;
    #pragma unroll
    for (int c = 0; c < CH; c++) acc += g_pooled[g * CH + c] * Wf[c];
    out[g] = acc / cnt + bf[0];
}

// ---------------- host -----------------------------------------------------

extern "C" void kernel_launch(void* const* d_in, const int* in_sizes, int n_in,
                              void* d_out, int out_size)
{
    const float* x   = (const float*)d_in[0];
    const float* xsc = (const float*)d_in[1];
    const float* W1  = (const float*)d_in[2];
    const float* b1  = (const float*)d_in[3];
    const float* W2  = (const float*)d_in[4];
    const float* b2  = (const float*)d_in[5];
    const float* We  = (const float*)d_in[6];
    const float* be  = (const float*)d_in[7];
    const float* W1s = (const float*)d_in[8];
    const float* b1s = (const float*)d_in[9];
    const float* W2s = (const float*)d_in[10];
    const float* b2s = (const float*)d_in[11];
    const float* Wes = (const float*)d_in[12];
    const float* bes = (const float*)d_in[13];
    const float* Wf  = (const float*)d_in[14];
    const float* bf  = (const float*)d_in[15];
    const int*   ei  = (const int*)d_in[16];
    const int*   bat = (const int*)d_in[17];

    int n  = in_sizes[0] / CH;
    int nE = in_sizes[16] / 2;
    const int* src = ei;
    const int* dst = ei + nE;
    float* out = (float*)d_out;

    float *hraw, *skip, *h;
    cudaGetSymbolAddress((void**)&hraw, g_hraw);
    cudaGetSymbolAddress((void**)&skip, g_skip);
    cudaGetSymbolAddress((void**)&h,    g_h);

    const int T = 256;
    int gN     = (n + T - 1) / T;
    int gE     = (nE + T - 1) / T;
    int gTile  = (n + 127) / 128;
    int gN16   = (n * 16 + T - 1) / T;
    int nB     = (n + 1023) / 1024;

    // CSR build
    k_zero<<<gN, T>>>(n);
    k_hist<<<gE, T>>>(dst, nE, bat, n);
    k_scan_p1<<<nB, 1024>>>(n);
    k_scan_p2<<<1, 64>>>(nB);
    k_scan_p3<<<nB, 1024>>>(n);
    k_place<<<gE, T>>>(src, dst, nE);

    // ---- branch 1 ----
    k_gemm2<<<gTile, T>>>(x, W1, We, be, n, hraw, skip);
    k_agg<0><<<gN16, T>>>(hraw, skip, h, b1, bat, n);
    k_gemm<<<gTile, T>>>(h, W2, n, hraw);
    k_agg<1><<<gN16, T>>>(hraw, h, h, b2, bat, n);

    // ---- branch 2 ----
    k_gemm2<<<gTile, T>>>(xsc, W1s, Wes, bes, n, hraw, skip);
    k_agg<0><<<gN16, T>>>(hraw, skip, h, b1s, bat, n);
    k_gemm<<<gTile, T>>>(h, W2s, n, hraw);
    k_agg<1><<<gN16, T>>>(hraw, h, h, b2s, bat, n);

    k_final<<<1, 64>>>(Wf, bf, out);
}

// round 10
// speedup vs baseline: 1.2091x; 1.2091x over previous
#include <cuda_runtime.h>
#include <cuda_bf16.h>

#define MAXN 50000
#define MAXE 800000
#define CH   64
#define NG   64

// ---------------- scratch (device globals) ---------------------------------
__device__ __align__(16) float g_dinv[MAXN];
__device__ __align__(16) float g_selfnorm[MAXN];
__device__ __align__(16) int   g_cnt_i[MAXN];
__device__ __align__(16) int   g_rowptr[MAXN + 1];
__device__ __align__(16) int   g_cursor[MAXN];
__device__ __align__(16) int   g_blocksum[64];
__device__ __align__(16) int   g_blockoff[64];
__device__ __align__(16) int2  g_cedge[MAXE];      // {src, w-as-int-bits}
__device__ __align__(16) float g_hraw[MAXN * CH];
__device__ __align__(16) __nv_bfloat16 g_hbf[MAXN * CH];   // bf16 mirror for gathers
__device__ __align__(16) float g_skip[MAXN * CH];
__device__ __align__(16) float g_h   [MAXN * CH];
__device__ __align__(16) float g_pooled[NG * CH];
__device__ __align__(16) float g_cntf[NG];

// ---------------- build CSR ------------------------------------------------

__global__ void k_zero(int n) {
    int i = blockIdx.x * blockDim.x + threadIdx.x;
    if (i < n)       g_cnt_i[i] = 0;
    if (i < NG * CH) g_pooled[i] = 0.0f;
    if (i < NG)      g_cntf[i] = 0.0f;
}

// degree histogram + per-graph node counts fused
__global__ void k_hist(const int* __restrict__ dst, int nE,
                       const int* __restrict__ batch, int n) {
    int e = blockIdx.x * blockDim.x + threadIdx.x;
    if (e < nE) atomicAdd(&g_cnt_i[dst[e]], 1);
    if (e < n)  atomicAdd(&g_cntf[batch[e]], 1.0f);
}

// scan pass 1 (block reduce) + dinv/selfnorm fused
__global__ void k_scan_p1(int n) {
    __shared__ int sh[1024];
    int i = blockIdx.x * 1024 + threadIdx.x;
    int c = (i < n) ? g_cnt_i[i] : 0;
    if (i < n) {
        float r = rsqrtf((float)c + 1.0f);   // deg incl. self-loop
        g_dinv[i] = r;
        g_selfnorm[i] = r * r;
    }
    sh[threadIdx.x] = c;
    __syncthreads();
    #pragma unroll
    for (int s = 512; s > 0; s >>= 1) {
        if (threadIdx.x < s) sh[threadIdx.x] += sh[threadIdx.x + s];
        __syncthreads();
    }
    if (threadIdx.x == 0) g_blocksum[blockIdx.x] = sh[0];
}

__global__ void k_scan_p2(int nB) {
    __shared__ int sh[64];
    int t = threadIdx.x;
    int v = (t < nB) ? g_blocksum[t] : 0;
    sh[t] = v;
    __syncthreads();
    #pragma unroll
    for (int off = 1; off < 64; off <<= 1) {
        int u = (t >= off) ? sh[t - off] : 0;
        __syncthreads();
        sh[t] += u;
        __syncthreads();
    }
    if (t < nB) g_blockoff[t] = sh[t] - v;   // exclusive
}

__global__ void k_scan_p3(int n) {
    __shared__ int sh[1024];
    int i = blockIdx.x * 1024 + threadIdx.x;
    int v = (i < n) ? g_cnt_i[i] : 0;
    sh[threadIdx.x] = v;
    __syncthreads();
    #pragma unroll
    for (int off = 1; off < 1024; off <<= 1) {
        int u = (threadIdx.x >= off) ? sh[threadIdx.x - off] : 0;
        __syncthreads();
        sh[threadIdx.x] += u;
        __syncthreads();
    }
    int ex = g_blockoff[blockIdx.x] + sh[threadIdx.x] - v;
    if (i < n) { g_rowptr[i] = ex; g_cursor[i] = ex; }
    if (i == n - 1) g_rowptr[n] = ex + v;
}

__global__ void k_place(const int* __restrict__ src, const int* __restrict__ dst, int nE) {
    int e = blockIdx.x * blockDim.x + threadIdx.x;
    if (e >= nE) return;
    int s = src[e], d = dst[e];
    int pos = atomicAdd(&g_cursor[d], 1);
    float w = g_dinv[s] * g_dinv[d];
    g_cedge[pos] = make_int2(s, __float_as_int(w));
}

// ---------------- bf16 pack helper -----------------------------------------
__device__ __forceinline__ uint2 pack_bf16x4(float4 v) {
    __nv_bfloat162 lo = __floats2bfloat162_rn(v.x, v.y);
    __nv_bfloat162 hi = __floats2bfloat162_rn(v.z, v.w);
    uint2 r;
    r.x = *(unsigned*)&lo;
    r.y = *(unsigned*)&hi;
    return r;
}

// ---------------- GEMM: X[n,64] @ W[64,64], 64-row tiles (round-6 proven) --
// OUT = X@W (fp32) and OUTBF = bf16(X@W)
__global__ void k_gemm(const float* __restrict__ X, const float* __restrict__ W,
                       int n, float* __restrict__ OUT, __nv_bfloat16* __restrict__ OUTBF)
{
    __shared__ __align__(16) float Ws[64 * 64];
    __shared__ __align__(16) float Xs[64 * 65];

    int tid = threadIdx.x;
    int row0 = blockIdx.x * 64;

    {
        const float4* W4 = (const float4*)W;
        float4* Ws4 = (float4*)Ws;
        for (int i = tid; i < 1024; i += 256) Ws4[i] = W4[i];
    }
    for (int i = tid; i < 1024; i += 256) {
        int r  = i >> 4;
        int c4 = (i & 15) << 2;
        int gr = row0 + r;
        float4 v = make_float4(0.f, 0.f, 0.f, 0.f);
        if (gr < n) v = *(const float4*)(X + gr * 64 + c4);
        float* p = &Xs[r * 65 + c4];
        p[0] = v.x; p[1] = v.y; p[2] = v.z; p[3] = v.w;
    }
    __syncthreads();

    int tx = tid & 15;
    int ty = tid >> 4;

    float a00=0,a01=0,a02=0,a03=0, a10=0,a11=0,a12=0,a13=0;
    float a20=0,a21=0,a22=0,a23=0, a30=0,a31=0,a32=0,a33=0;

    #pragma unroll
    for (int k = 0; k < 64; k++) {
        float4 w = *(const float4*)&Ws[k * 64 + tx * 4];
        float x0 = Xs[(ty * 4 + 0) * 65 + k];
        float x1 = Xs[(ty * 4 + 1) * 65 + k];
        float x2 = Xs[(ty * 4 + 2) * 65 + k];
        float x3 = Xs[(ty * 4 + 3) * 65 + k];
        a00 = fmaf(x0, w.x, a00); a01 = fmaf(x0, w.y, a01);
        a02 = fmaf(x0, w.z, a02); a03 = fmaf(x0, w.w, a03);
        a10 = fmaf(x1, w.x, a10); a11 = fmaf(x1, w.y, a11);
        a12 = fmaf(x1, w.z, a12); a13 = fmaf(x1, w.w, a13);
        a20 = fmaf(x2, w.x, a20); a21 = fmaf(x2, w.y, a21);
        a22 = fmaf(x2, w.z, a22); a23 = fmaf(x2, w.w, a23);
        a30 = fmaf(x3, w.x, a30); a31 = fmaf(x3, w.y, a31);
        a32 = fmaf(x3, w.z, a32); a33 = fmaf(x3, w.w, a33);
    }

    int c0 = tx * 4;
    float rows[4][4] = {{a00,a01,a02,a03},{a10,a11,a12,a13},
                        {a20,a21,a22,a23},{a30,a31,a32,a33}};
    #pragma unroll
    for (int i = 0; i < 4; i++) {
        int r = row0 + ty * 4 + i;
        if (r >= n) break;
        float4 v = make_float4(rows[i][0], rows[i][1], rows[i][2], rows[i][3]);
        *(float4*)(OUT + r * 64 + c0) = v;
        *(uint2*)(OUTBF + r * 64 + c0) = pack_bf16x4(v);
    }
}

// ---------------- dual GEMM: OUTa = X@Wa (fp32 + bf16), OUTb = relu(X@Wb+bb)
__global__ void k_gemm2(const float* __restrict__ X,
                        const float* __restrict__ Wa,
                        const float* __restrict__ Wb, const float* __restrict__ bb,
                        int n, float* __restrict__ OUTa, __nv_bfloat16* __restrict__ OUTaBF,
                        float* __restrict__ OUTb)
{
    __shared__ __align__(16) float Wsa[64 * 64];
    __shared__ __align__(16) float Wsb[64 * 64];
    __shared__ __align__(16) float Xs[64 * 65];

    int tid = threadIdx.x;
    int row0 = blockIdx.x * 64;

    {
        const float4* Wa4 = (const float4*)Wa;
        const float4* Wb4 = (const float4*)Wb;
        float4* a4 = (float4*)Wsa;
        float4* b4 = (float4*)Wsb;
        for (int i = tid; i < 1024; i += 256) { a4[i] = Wa4[i]; b4[i] = Wb4[i]; }
    }
    for (int i = tid; i < 1024; i += 256) {
        int r  = i >> 4;
        int c4 = (i & 15) << 2;
        int gr = row0 + r;
        float4 v = make_float4(0.f, 0.f, 0.f, 0.f);
        if (gr < n) v = *(const float4*)(X + gr * 64 + c4);
        float* p = &Xs[r * 65 + c4];
        p[0] = v.x; p[1] = v.y; p[2] = v.z; p[3] = v.w;
    }
    __syncthreads();

    int tx = tid & 15;
    int ty = tid >> 4;

    float A[4][4] = {}, B[4][4] = {};

    #pragma unroll
    for (int k = 0; k < 64; k++) {
        float4 wa = *(const float4*)&Wsa[k * 64 + tx * 4];
        float4 wb = *(const float4*)&Wsb[k * 64 + tx * 4];
        float xr[4];
        #pragma unroll
        for (int i = 0; i < 4; i++) xr[i] = Xs[(ty * 4 + i) * 65 + k];
        #pragma unroll
        for (int i = 0; i < 4; i++) {
            A[i][0] = fmaf(xr[i], wa.x, A[i][0]);
            A[i][1] = fmaf(xr[i], wa.y, A[i][1]);
            A[i][2] = fmaf(xr[i], wa.z, A[i][2]);
            A[i][3] = fmaf(xr[i], wa.w, A[i][3]);
            B[i][0] = fmaf(xr[i], wb.x, B[i][0]);
            B[i][1] = fmaf(xr[i], wb.y, B[i][1]);
            B[i][2] = fmaf(xr[i], wb.z, B[i][2]);
            B[i][3] = fmaf(xr[i], wb.w, B[i][3]);
        }
    }

    int c0 = tx * 4;
    float4 bv = *(const float4*)(bb + c0);
    #pragma unroll
    for (int i = 0; i < 4; i++) {
        int r = row0 + ty * 4 + i;
        if (r >= n) break;
        float4 va = make_float4(A[i][0], A[i][1], A[i][2], A[i][3]);
        *(float4*)(OUTa + r * 64 + c0) = va;
        *(uint2*)(OUTaBF + r * 64 + c0) = pack_bf16x4(va);
        *(float4*)(OUTb + r * 64 + c0) =
            make_float4(fmaxf(B[i][0] + bv.x, 0.f), fmaxf(B[i][1] + bv.y, 0.f),
                        fmaxf(B[i][2] + bv.z, 0.f), fmaxf(B[i][3] + bv.w, 0.f));
    }
}

// ---------------- fused GCN aggregate --------------------------------------
// OUT[d] = relu( sum_e w_e*Hbf[src_e] + selfnorm[d]*H[d] + b ) + SKIP[d]
// Neighbor gathers from bf16 mirror (half the L2 traffic); self term fp32.
// if DO_POOL: red-add OUT row into g_pooled[batch[d]]. 16 threads/node.
template<int DO_POOL>
__global__ void k_agg(const float* __restrict__ H, const __nv_bfloat16* __restrict__ Hbf,
                      const float* __restrict__ SKIP,
                      float* __restrict__ OUT, const float* __restrict__ b,
                      const int* __restrict__ batch, int n)
{
    int t = blockIdx.x * blockDim.x + threadIdx.x;
    int node = t >> 4;
    if (node >= n) return;
    int c4 = (t & 15) << 2;

    int beg = g_rowptr[node];
    int end = g_rowptr[node + 1];

    float sn = g_selfnorm[node];
    float4 hd = *(const float4*)(H + node * 64 + c4);
    float4 acc = make_float4(sn * hd.x, sn * hd.y, sn * hd.z, sn * hd.w);

    for (int j = beg; j < end; j++) {
        int2 e = __ldg(&g_cedge[j]);                 // broadcast in group
        float w = __int_as_float(e.y);
        uint2 raw = *(const uint2*)(Hbf + e.x * 64 + c4);   // 8B gather
        __nv_bfloat162 p0 = *(__nv_bfloat162*)&raw.x;
        __nv_bfloat162 p1 = *(__nv_bfloat162*)&raw.y;
        float2 f0 = __bfloat1622float2(p0);
        float2 f1 = __bfloat1622float2(p1);
        acc.x = fmaf(w, f0.x, acc.x);
        acc.y = fmaf(w, f0.y, acc.y);
        acc.z = fmaf(w, f1.x, acc.z);
        acc.w = fmaf(w, f1.y, acc.w);
    }

    float4 bv = *(const float4*)(b + c4);
    float4 sk = *(const float4*)(SKIP + node * 64 + c4);
    float4 o = make_float4(fmaxf(acc.x + bv.x, 0.f) + sk.x,
                           fmaxf(acc.y + bv.y, 0.f) + sk.y,
                           fmaxf(acc.z + bv.z, 0.f) + sk.z,
                           fmaxf(acc.w + bv.w, 0.f) + sk.w);
    *(float4*)(OUT + node * 64 + c4) = o;

    if (DO_POOL) {
        int g = batch[node];
        float* p = g_pooled + g * 64 + c4;
        asm volatile("red.global.add.v4.f32 [%0], {%1,%2,%3,%4};"
                     :: "l"(p), "f"(o.x), "f"(o.y), "f"(o.z), "f"(o.w)
                     : "memory");
    }
}

__global__ void k_final(const float* __restrict__ Wf, const float* __restrict__ bf,
                        float* __restrict__ out)
{
    int g = threadIdx.x;
    if (g >= NG) return;
    float cnt = fmaxf(g_cntf[g], 1.0f);
    float acc = 0.f;
    #pragma unroll
    for (int c = 0; c < CH; c++) acc += g_pooled[g * CH + c] * Wf[c];
    out[g] = acc / cnt + bf[0];
}

// ---------------- host -----------------------------------------------------

extern "C" void kernel_launch(void* const* d_in, const int* in_sizes, int n_in,
                              void* d_out, int out_size)
{
    const float* x   = (const float*)d_in[0];
    const float* xsc = (const float*)d_in[1];
    const float* W1  = (const float*)d_in[2];
    const float* b1  = (const float*)d_in[3];
    const float* W2  = (const float*)d_in[4];
    const float* b2  = (const float*)d_in[5];
    const float* We  = (const float*)d_in[6];
    const float* be  = (const float*)d_in[7];
    const float* W1s = (const float*)d_in[8];
    const float* b1s = (const float*)d_in[9];
    const float* W2s = (const float*)d_in[10];
    const float* b2s = (const float*)d_in[11];
    const float* Wes = (const float*)d_in[12];
    const float* bes = (const float*)d_in[13];
    const float* Wf  = (const float*)d_in[14];
    const float* bf  = (const float*)d_in[15];
    const int*   ei  = (const int*)d_in[16];
    const int*   bat = (const int*)d_in[17];

    int n  = in_sizes[0] / CH;
    int nE = in_sizes[16] / 2;
    const int* src = ei;
    const int* dst = ei + nE;
    float* out = (float*)d_out;

    float *hraw, *skip, *h;
    __nv_bfloat16* hbf;
    cudaGetSymbolAddress((void**)&hraw, g_hraw);
    cudaGetSymbolAddress((void**)&hbf,  g_hbf);
    cudaGetSymbolAddress((void**)&skip, g_skip);
    cudaGetSymbolAddress((void**)&h,    g_h);

    const int T = 256;
    int gN     = (n + T - 1) / T;
    int gE     = (nE + T - 1) / T;
    int gTile  = (n + 63) / 64;
    int gN16   = (n * 16 + T - 1) / T;
    int nB     = (n + 1023) / 1024;

    // CSR build
    k_zero<<<gN, T>>>(n);
    k_hist<<<gE, T>>>(dst, nE, bat, n);
    k_scan_p1<<<nB, 1024>>>(n);
    k_scan_p2<<<1, 64>>>(nB);
    k_scan_p3<<<nB, 1024>>>(n);
    k_place<<<gE, T>>>(src, dst, nE);

    // ---- branch 1 ----
    k_gemm2<<<gTile, T>>>(x, W1, We, be, n, hraw, hbf, skip);
    k_agg<0><<<gN16, T>>>(hraw, hbf, skip, h, b1, bat, n);
    k_gemm<<<gTile, T>>>(h, W2, n, hraw, hbf);
    k_agg<1><<<gN16, T>>>(hraw, hbf, h, h, b2, bat, n);

    // ---- branch 2 ----
    k_gemm2<<<gTile, T>>>(xsc, W1s, Wes, bes, n, hraw, hbf, skip);
    k_agg<0><<<gN16, T>>>(hraw, hbf, skip, h, b1s, bat, n);
    k_gemm<<<gTile, T>>>(h, W2s, n, hraw, hbf);
    k_agg<1><<<gN16, T>>>(hraw, hbf, h, h, b2s, bat, n);

    k_final<<<1, 64>>>(Wf, bf, out);
}